// round 13
// baseline (speedup 1.0000x reference)
#include <cuda_runtime.h>
#include <cuda_bf16.h>
#include <stdint.h>
#include <math.h>

#define DIMN 512
#define SEQ 4096
#define NB 2
#define NH 8
#define DH 64
#define ROWSZ (NB*SEQ)   /* 8192 */
#define QSCALE (0.125f * 1.4426950408889634f) /* fold 1/sqrt(64) * log2(e) */

typedef __nv_bfloat16 bf16;

// ---------------- scratch (device globals; no allocs allowed) ---------------
__device__ bf16 g_xh[ROWSZ*DIMN], g_xl[ROWSZ*DIMN];
__device__ bf16 g_ch[ROWSZ*DIMN], g_cl[ROWSZ*DIMN];
__device__ bf16 g_qh[ROWSZ*DIMN], g_ql[ROWSZ*DIMN];
__device__ bf16 g_kh[ROWSZ*DIMN], g_kl[ROWSZ*DIMN];
__device__ bf16 g_vh[ROWSZ*DIMN], g_vl[ROWSZ*DIMN];
__device__ bf16 g_ah[ROWSZ*DIMN], g_al[ROWSZ*DIMN];
__device__ bf16 g_wqh[DIMN*DIMN], g_wql[DIMN*DIMN];
__device__ bf16 g_wkh[DIMN*DIMN], g_wkl[DIMN*DIMN];
__device__ bf16 g_wvh[DIMN*DIMN], g_wvl[DIMN*DIMN];
__device__ bf16 g_woh[DIMN*DIMN], g_wol[DIMN*DIMN];

// ---------------- helpers ----------------------------------------------------
__device__ __forceinline__ uint32_t sm_u32(const void* p) {
    uint32_t a;
    asm("{ .reg .u64 t; cvta.to.shared.u64 t, %1; cvt.u32.u64 %0, t; }"
        : "=r"(a) : "l"(p));
    return a;
}
__device__ __forceinline__ void ldsm4(uint32_t* r, uint32_t a) {
    asm volatile("ldmatrix.sync.aligned.m8n8.x4.shared.b16 {%0,%1,%2,%3}, [%4];"
                 : "=r"(r[0]), "=r"(r[1]), "=r"(r[2]), "=r"(r[3]) : "r"(a));
}
__device__ __forceinline__ void ldsm4t(uint32_t* r, uint32_t a) {
    asm volatile("ldmatrix.sync.aligned.m8n8.x4.trans.shared.b16 {%0,%1,%2,%3}, [%4];"
                 : "=r"(r[0]), "=r"(r[1]), "=r"(r[2]), "=r"(r[3]) : "r"(a));
}
__device__ __forceinline__ void mma_bf(float* c, const uint32_t* a, uint32_t b0,
                                       uint32_t b1) {
    asm volatile(
        "mma.sync.aligned.m16n8k16.row.col.f32.bf16.bf16.f32 "
        "{%0,%1,%2,%3}, {%4,%5,%6,%7}, {%8,%9}, {%0,%1,%2,%3};"
        : "+f"(c[0]), "+f"(c[1]), "+f"(c[2]), "+f"(c[3])
        : "r"(a[0]), "r"(a[1]), "r"(a[2]), "r"(a[3]), "r"(b0), "r"(b1));
}
__device__ __forceinline__ float ex2f(float x) {
    float y;
    asm("ex2.approx.ftz.f32 %0, %1;" : "=f"(y) : "f"(x));
    return y;
}
// pack: result.lo = a, result.hi = b
__device__ __forceinline__ uint32_t packbf(float a, float b) {
    uint32_t r;
    asm("cvt.rn.satfinite.bf16x2.f32 %0, %1, %2;" : "=r"(r) : "f"(b), "f"(a));
    return r;
}
__device__ __forceinline__ float lo_f(uint32_t h) { return __uint_as_float(h << 16); }
__device__ __forceinline__ float hi_f(uint32_t h) {
    return __uint_as_float(h & 0xffff0000u);
}
__device__ __forceinline__ void cpa16cg(uint32_t dst, const void* src) {
    asm volatile("cp.async.cg.shared.global [%0], [%1], 16;"
                 :: "r"(dst), "l"(__cvta_generic_to_global(src)));
}
#define CP_COMMIT asm volatile("cp.async.commit_group;" ::: "memory")
#define CP_WAIT0  asm volatile("cp.async.wait_group 0;" ::: "memory")
#define CP_WAIT1  asm volatile("cp.async.wait_group 1;" ::: "memory")

// swizzled offset for 16B chunk c in 128B row r
#define SWZ(r, c) ((uint32_t)((r) * 128) + ((uint32_t)((c) ^ ((r) & 7)) << 4))

// ---------------------------------------------------------------------------
// split fp32 -> bf16 hi + lo (x ~= hi + lo). merged variants.
// ---------------------------------------------------------------------------
__device__ __forceinline__ void split_body(const float* __restrict__ s,
                                           bf16* __restrict__ h,
                                           bf16* __restrict__ l) {
    int i = (blockIdx.x * 256 + threadIdx.x) * 4;
    float4 v = *(const float4*)&s[i];
    uint32_t h01 = packbf(v.x, v.y);
    uint32_t h23 = packbf(v.z, v.w);
    uint32_t l01 = packbf(v.x - lo_f(h01), v.y - hi_f(h01));
    uint32_t l23 = packbf(v.z - lo_f(h23), v.w - hi_f(h23));
    *(uint2*)&h[i] = make_uint2(h01, h23);
    *(uint2*)&l[i] = make_uint2(l01, l23);
}
__global__ __launch_bounds__(256) void split_x2(
    const float* __restrict__ s0, bf16* __restrict__ h0, bf16* __restrict__ l0,
    const float* __restrict__ s1, bf16* __restrict__ h1, bf16* __restrict__ l1) {
    if (blockIdx.y == 0) split_body(s0, h0, l0);
    else                 split_body(s1, h1, l1);
}
__global__ __launch_bounds__(256) void split_w4(
    const float* __restrict__ s0, bf16* __restrict__ h0, bf16* __restrict__ l0,
    const float* __restrict__ s1, bf16* __restrict__ h1, bf16* __restrict__ l1,
    const float* __restrict__ s2, bf16* __restrict__ h2, bf16* __restrict__ l2,
    const float* __restrict__ s3, bf16* __restrict__ h3, bf16* __restrict__ l3) {
    switch (blockIdx.y) {
        case 0: split_body(s0, h0, l0); break;
        case 1: split_body(s1, h1, l1); break;
        case 2: split_body(s2, h2, l2); break;
        default: split_body(s3, h3, l3); break;
    }
}

// ---------------------------------------------------------------------------
// bf16-split x3 GEMM, 128x64 tile, 256 threads (8 warps x 16 rows),
// 2-stage cp.async pipeline, 128B swizzled rows.
// Stage (48 KB): Ah +0 (16K), Al +16384, Wh +32768 (8K), Wl +40960.
// ---------------------------------------------------------------------------
#define GST 49152
#define GEMM_SMEM (2 * GST)   /* 98304 -> 2 CTAs/SM, 16 warps */

__global__ __launch_bounds__(256, 2) void gemm_tc(
    const bf16* __restrict__ Ah, const bf16* __restrict__ Al,
    const bf16* __restrict__ Wh, const bf16* __restrict__ Wl,
    bf16* __restrict__ Ch, bf16* __restrict__ Cl,
    float* __restrict__ Cf, const float* __restrict__ bias, float scale) {
    extern __shared__ char smem[];
    const uint32_t sb = sm_u32(smem);
    const int tid = threadIdx.x, w = tid >> 5, l = tid & 31;
    const int m0 = blockIdx.x * 128, n0 = blockIdx.y * 64;

    auto issue = [&](int kc, uint32_t stb) {
#pragma unroll
        for (int p = 0; p < 12; p++) {
            int li = tid + 256 * p;
            if (li < 2048) {  // A: 128 rows x 8 chunks x 2 arrays
                int arr = li >> 10;
                int rem = li & 1023;
                int r = rem >> 3, c = rem & 7;
                const bf16* base = arr ? Al : Ah;
                cpa16cg(sb + stb + (uint32_t)arr * 16384 + SWZ(r, c),
                        base + (size_t)(m0 + r) * DIMN + kc * 64 + c * 8);
            } else {          // W: 64 rows x 8 chunks x 2 arrays
                int li2 = li - 2048;
                int arr = li2 >> 9;
                int rem = li2 & 511;
                int r = rem >> 3, c = rem & 7;
                const bf16* base = arr ? Wl : Wh;
                cpa16cg(sb + stb + 32768u + (uint32_t)arr * 8192 + SWZ(r, c),
                        base + (size_t)(n0 + r) * DIMN + kc * 64 + c * 8);
            }
        }
        CP_COMMIT;
    };

    float acc[8][4];
#pragma unroll
    for (int i = 0; i < 8; i++)
#pragma unroll
        for (int j = 0; j < 4; j++) acc[i][j] = 0.f;

    issue(0, 0);
    for (int kc = 0; kc < 8; kc++) {
        if (kc + 1 < 8) {
            issue(kc + 1, (uint32_t)((kc + 1) & 1) * GST);
            CP_WAIT1;
        } else {
            CP_WAIT0;
        }
        __syncthreads();
        const uint32_t stb = sb + (uint32_t)(kc & 1) * GST;

        uint32_t ah[16], al[16];
#pragma unroll
        for (int kt = 0; kt < 4; kt++) {
            int row = w * 16 + (l & 15);
            int cc = kt * 2 + (l >> 4);
            uint32_t aa = stb + SWZ(row, cc);
            ldsm4(&ah[kt * 4], aa);
            ldsm4(&al[kt * 4], aa + 16384);
        }
#pragma unroll
        for (int ntp = 0; ntp < 4; ntp++) {
#pragma unroll
            for (int kt = 0; kt < 4; kt++) {
                uint32_t bh[4], bl[4];
                int row = ntp * 16 + ((l >> 4) << 3) + (l & 7);
                int cc = kt * 2 + ((l >> 3) & 1);
                uint32_t ba = stb + 32768u + SWZ(row, cc);
                ldsm4(bh, ba);
                ldsm4(bl, ba + 8192);
                mma_bf(acc[2 * ntp], &ah[kt * 4], bh[0], bh[1]);
                mma_bf(acc[2 * ntp], &ah[kt * 4], bl[0], bl[1]);
                mma_bf(acc[2 * ntp], &al[kt * 4], bh[0], bh[1]);
                mma_bf(acc[2 * ntp + 1], &ah[kt * 4], bh[2], bh[3]);
                mma_bf(acc[2 * ntp + 1], &ah[kt * 4], bl[2], bl[3]);
                mma_bf(acc[2 * ntp + 1], &al[kt * 4], bh[2], bh[3]);
            }
        }
        __syncthreads();
    }

    const int r0 = m0 + w * 16 + (l >> 2);
    const int c0 = n0 + 2 * (l & 3);
#pragma unroll
    for (int nt = 0; nt < 8; nt++) {
        int cc = c0 + nt * 8;
        float v0 = acc[nt][0] * scale, v1 = acc[nt][1] * scale;
        float v2 = acc[nt][2] * scale, v3 = acc[nt][3] * scale;
        if (bias) {
            float b0 = bias[cc], b1 = bias[cc + 1];
            v0 += b0; v1 += b1; v2 += b0; v3 += b1;
        }
        if (Cf) {
            *(float2*)&Cf[(size_t)r0 * DIMN + cc] = make_float2(v0, v1);
            *(float2*)&Cf[(size_t)(r0 + 8) * DIMN + cc] = make_float2(v2, v3);
        } else {
            uint32_t h01 = packbf(v0, v1);
            uint32_t h23 = packbf(v2, v3);
            uint32_t l01 = packbf(v0 - lo_f(h01), v1 - hi_f(h01));
            uint32_t l23 = packbf(v2 - lo_f(h23), v3 - hi_f(h23));
            *(uint32_t*)&Ch[(size_t)r0 * DIMN + cc] = h01;
            *(uint32_t*)&Ch[(size_t)(r0 + 8) * DIMN + cc] = h23;
            *(uint32_t*)&Cl[(size_t)r0 * DIMN + cc] = l01;
            *(uint32_t*)&Cl[(size_t)(r0 + 8) * DIMN + cc] = l23;
        }
    }
}

// ---------------------------------------------------------------------------
// Flash attention, bf16-split x3, log2-domain softmax, 128 q-rows per CTA,
// 256 threads (8 warps x 16 rows). 2-stage pipeline, Q overlaid in stage 1.
// Stage (32 KB): KH +0, KL +8192, VH +16384, VL +24576. 64 KB total.
// S and O interleaved per 16-KV-col block to keep registers under 128.
// ---------------------------------------------------------------------------
#define NCHUNK (SEQ / 64)
#define STG 32768
#define ATT_SMEM (2 * STG)   /* 65536 -> 2 CTAs/SM, 16 warps */

__global__ __launch_bounds__(256, 2) void attn_tc(
    const bf16* __restrict__ Qh, const bf16* __restrict__ Ql,
    const bf16* __restrict__ Kh, const bf16* __restrict__ Kl,
    const bf16* __restrict__ Vh, const bf16* __restrict__ Vl,
    bf16* __restrict__ Ahi, bf16* __restrict__ Alo) {
    extern __shared__ char smem[];
    const uint32_t sb = sm_u32(smem);
    const int tid = threadIdx.x, w = tid >> 5, l = tid & 31;
    const int q0 = blockIdx.x * 128;
    const int h = blockIdx.y, b = blockIdx.z;
    const size_t headoff = (size_t)h * DH;
    const size_t qrow0 = (size_t)(b * SEQ + q0);
    const size_t krow0 = (size_t)(b * SEQ);

    auto kvissue = [&](int chunk, uint32_t stb) {
#pragma unroll
        for (int p = 0; p < 8; p++) {
            int li = tid + 256 * p;
            int arr = li >> 9;
            int rem = li & 511;
            int r = rem >> 3, c = rem & 7;
            const bf16* base = (arr == 0) ? Kh : (arr == 1) ? Kl : (arr == 2) ? Vh : Vl;
            cpa16cg(sb + stb + (uint32_t)arr * 8192 + SWZ(r, c),
                    base + (krow0 + chunk * 64 + r) * DIMN + headoff + c * 8);
        }
        CP_COMMIT;
    };

    // Q (hi/lo, 128 rows) into stage 1; chunk 0 into stage 0
#pragma unroll
    for (int p = 0; p < 8; p++) {
        int li = tid + 256 * p;
        int arr = li >> 10;
        int rem = li & 1023;
        int r = rem >> 3, c = rem & 7;
        const bf16* src = (arr ? Ql : Qh) + (qrow0 + r) * DIMN + headoff + c * 8;
        cpa16cg(sb + STG + (uint32_t)arr * 16384 + SWZ(r, c), src);
    }
    CP_COMMIT;
    kvissue(0, 0);
    CP_WAIT0;
    __syncthreads();

    // extract Q fragments from stage 1 (held in registers for all chunks)
    uint32_t aqh[16], aql[16];
#pragma unroll
    for (int kt = 0; kt < 4; kt++) {
        int row = w * 16 + (l & 15);
        int cc = kt * 2 + (l >> 4);
        uint32_t aa = sb + STG + SWZ(row, cc);
        ldsm4(&aqh[kt * 4], aa);
        ldsm4(&aql[kt * 4], aa + 16384);
    }
    __syncthreads();  // stage 1 free -> prefetch chunk 1 into it
    kvissue(1, STG);

    float o[8][4];
#pragma unroll
    for (int i = 0; i < 8; i++)
#pragma unroll
        for (int j = 0; j < 4; j++) o[i][j] = 0.f;
    float ls0 = 0.f, ls1 = 0.f;

    for (int ch = 0; ch < NCHUNK; ch++) {
        if (ch + 1 < NCHUNK) CP_WAIT1; else CP_WAIT0;
        __syncthreads();
        const uint32_t stb = sb + (uint32_t)(ch & 1) * STG;

#pragma unroll
        for (int kb = 0; kb < 4; kb++) {
            // ---- S block: my 16 rows x KV cols [kb*16, kb*16+16) ----
            float s[8];
#pragma unroll
            for (int i = 0; i < 8; i++) s[i] = 0.f;
#pragma unroll
            for (int kt = 0; kt < 4; kt++) {
                uint32_t bh[4], bl[4];
                int row = kb * 16 + ((l >> 4) << 3) + (l & 7);
                int cc = kt * 2 + ((l >> 3) & 1);
                uint32_t ba = stb + SWZ(row, cc);
                ldsm4(bh, ba);
                ldsm4(bl, ba + 8192);
                mma_bf(s, &aqh[kt * 4], bh[0], bh[1]);
                mma_bf(s, &aqh[kt * 4], bl[0], bl[1]);
                mma_bf(s, &aql[kt * 4], bh[0], bh[1]);
                mma_bf(s + 4, &aqh[kt * 4], bh[2], bh[3]);
                mma_bf(s + 4, &aqh[kt * 4], bl[2], bl[3]);
                mma_bf(s + 4, &aql[kt * 4], bh[2], bh[3]);
            }

            // ---- p = 2^s; split to bf16 hi/lo (A-fragment for this kb) ----
            uint32_t pah[4], pal[4];
            {
                float p0 = ex2f(s[0]), p1 = ex2f(s[1]);
                float p2 = ex2f(s[2]), p3 = ex2f(s[3]);
                ls0 += p0 + p1; ls1 += p2 + p3;
                uint32_t h01 = packbf(p0, p1), h23 = packbf(p2, p3);
                pah[0] = h01; pah[1] = h23;
                pal[0] = packbf(p0 - lo_f(h01), p1 - hi_f(h01));
                pal[1] = packbf(p2 - lo_f(h23), p3 - hi_f(h23));
                p0 = ex2f(s[4]); p1 = ex2f(s[5]);
                p2 = ex2f(s[6]); p3 = ex2f(s[7]);
                ls0 += p0 + p1; ls1 += p2 + p3;
                h01 = packbf(p0, p1); h23 = packbf(p2, p3);
                pah[2] = h01; pah[3] = h23;
                pal[2] = packbf(p0 - lo_f(h01), p1 - hi_f(h01));
                pal[3] = packbf(p2 - lo_f(h23), p3 - hi_f(h23));
            }

            // ---- O += P_kb @ V_kb ----
#pragma unroll
            for (int ntp = 0; ntp < 4; ntp++) {
                uint32_t vh[4], vl[4];
                int row = kb * 16 + (l & 7) + ((l >> 3) & 1) * 8;
                int cc = ntp * 2 + (l >> 4);
                uint32_t va = stb + 16384u + SWZ(row, cc);
                ldsm4t(vh, va);
                ldsm4t(vl, va + 8192);
                mma_bf(o[2 * ntp], pah, vh[0], vh[1]);
                mma_bf(o[2 * ntp], pah, vl[0], vl[1]);
                mma_bf(o[2 * ntp], pal, vh[0], vh[1]);
                mma_bf(o[2 * ntp + 1], pah, vh[2], vh[3]);
                mma_bf(o[2 * ntp + 1], pah, vl[2], vl[3]);
                mma_bf(o[2 * ntp + 1], pal, vh[2], vh[3]);
            }
        }
        __syncthreads();  // all warps done with stage (ch&1)
        if (ch + 2 < NCHUNK) kvissue(ch + 2, (uint32_t)(ch & 1) * STG);
    }

    // row-sum reduce across the quad (threads sharing a row)
#pragma unroll
    for (int off = 1; off <= 2; off <<= 1) {
        ls0 += __shfl_xor_sync(0xffffffffu, ls0, off);
        ls1 += __shfl_xor_sync(0xffffffffu, ls1, off);
    }
    const float i0 = 1.0f / ls0, i1 = 1.0f / ls1;
    const size_t r0 = qrow0 + w * 16 + (l >> 2);
    const int c0 = (int)headoff + 2 * (l & 3);
#pragma unroll
    for (int nt = 0; nt < 8; nt++) {
        int cc = c0 + nt * 8;
        float p0 = o[nt][0] * i0, p1 = o[nt][1] * i0;
        float p2 = o[nt][2] * i1, p3 = o[nt][3] * i1;
        uint32_t h01 = packbf(p0, p1);
        uint32_t h23 = packbf(p2, p3);
        uint32_t l01 = packbf(p0 - lo_f(h01), p1 - hi_f(h01));
        uint32_t l23 = packbf(p2 - lo_f(h23), p3 - hi_f(h23));
        *(uint32_t*)&Ahi[r0 * DIMN + cc] = h01;
        *(uint32_t*)&Ahi[(r0 + 8) * DIMN + cc] = h23;
        *(uint32_t*)&Alo[r0 * DIMN + cc] = l01;
        *(uint32_t*)&Alo[(r0 + 8) * DIMN + cc] = l23;
    }
}

// ---------------------------------------------------------------------------
extern "C" void kernel_launch(void* const* d_in, const int* in_sizes, int n_in,
                              void* d_out, int out_size) {
    const float* x     = (const float*)d_in[0];
    const float* ctx   = (const float*)d_in[1];
    const float* w_q   = (const float*)d_in[2];
    const float* w_k   = (const float*)d_in[3];
    const float* w_v   = (const float*)d_in[4];
    const float* w_out = (const float*)d_in[5];
    const float* b_out = (const float*)d_in[6];
    float* out = (float*)d_out;

    bf16 *xh, *xl, *ch, *cl, *qh, *ql, *kh, *kl, *vh, *vl, *ah, *al;
    bf16 *wqh, *wql, *wkh, *wkl, *wvh, *wvl, *woh, *wol;
    cudaGetSymbolAddress((void**)&xh, g_xh);   cudaGetSymbolAddress((void**)&xl, g_xl);
    cudaGetSymbolAddress((void**)&ch, g_ch);   cudaGetSymbolAddress((void**)&cl, g_cl);
    cudaGetSymbolAddress((void**)&qh, g_qh);   cudaGetSymbolAddress((void**)&ql, g_ql);
    cudaGetSymbolAddress((void**)&kh, g_kh);   cudaGetSymbolAddress((void**)&kl, g_kl);
    cudaGetSymbolAddress((void**)&vh, g_vh);   cudaGetSymbolAddress((void**)&vl, g_vl);
    cudaGetSymbolAddress((void**)&ah, g_ah);   cudaGetSymbolAddress((void**)&al, g_al);
    cudaGetSymbolAddress((void**)&wqh, g_wqh); cudaGetSymbolAddress((void**)&wql, g_wql);
    cudaGetSymbolAddress((void**)&wkh, g_wkh); cudaGetSymbolAddress((void**)&wkl, g_wkl);
    cudaGetSymbolAddress((void**)&wvh, g_wvh); cudaGetSymbolAddress((void**)&wvl, g_wvl);
    cudaGetSymbolAddress((void**)&woh, g_woh); cudaGetSymbolAddress((void**)&wol, g_wol);

    cudaFuncSetAttribute(attn_tc, cudaFuncAttributeMaxDynamicSharedMemorySize,
                         ATT_SMEM);
    cudaFuncSetAttribute(gemm_tc, cudaFuncAttributeMaxDynamicSharedMemorySize,
                         GEMM_SMEM);

    const int nbig = ROWSZ * DIMN / 1024;   // 4096 blocks
    const int nsml = DIMN * DIMN / 1024;    // 256 blocks
    split_x2<<<dim3(nbig, 2), 256>>>(x, xh, xl, ctx, ch, cl);
    split_w4<<<dim3(nsml, 4), 256>>>(w_q, wqh, wql, w_k, wkh, wkl,
                                     w_v, wvh, wvl, w_out, woh, wol);

    dim3 gg(ROWSZ / 128, DIMN / 64);
    gemm_tc<<<gg, 256, GEMM_SMEM>>>(xh, xl, wqh, wql, qh, ql, nullptr, nullptr, QSCALE);
    gemm_tc<<<gg, 256, GEMM_SMEM>>>(ch, cl, wkh, wkl, kh, kl, nullptr, nullptr, 1.0f);
    gemm_tc<<<gg, 256, GEMM_SMEM>>>(ch, cl, wvh, wvl, vh, vl, nullptr, nullptr, 1.0f);

    attn_tc<<<dim3(SEQ / 128, NH, NB), 256, ATT_SMEM>>>(qh, ql, kh, kl, vh, vl,
                                                        ah, al);

    gemm_tc<<<gg, 256, GEMM_SMEM>>>(ah, al, woh, wol, nullptr, nullptr, out, b_out, 1.0f);
}

// round 17
// speedup vs baseline: 1.1060x; 1.1060x over previous
#include <cuda_runtime.h>
#include <cuda_bf16.h>
#include <stdint.h>
#include <math.h>

#define DIMN 512
#define SEQ 4096
#define NB 2
#define NH 8
#define DH 64
#define ROWSZ (NB*SEQ)   /* 8192 */
#define QSCALE (0.125f * 1.4426950408889634f) /* fold 1/sqrt(64) * log2(e) */

typedef __nv_bfloat16 bf16;

// ---------------- scratch (device globals; no allocs allowed) ---------------
__device__ bf16 g_xh[ROWSZ*DIMN], g_xl[ROWSZ*DIMN];
__device__ bf16 g_ch[ROWSZ*DIMN], g_cl[ROWSZ*DIMN];
__device__ bf16 g_qh[ROWSZ*DIMN], g_ql[ROWSZ*DIMN];
__device__ bf16 g_kh[ROWSZ*DIMN], g_kl[ROWSZ*DIMN];
__device__ bf16 g_vh[ROWSZ*DIMN], g_vl[ROWSZ*DIMN];
__device__ bf16 g_ah[ROWSZ*DIMN], g_al[ROWSZ*DIMN];
__device__ bf16 g_wqh[DIMN*DIMN], g_wql[DIMN*DIMN];
__device__ bf16 g_wkh[DIMN*DIMN], g_wkl[DIMN*DIMN];
__device__ bf16 g_wvh[DIMN*DIMN], g_wvl[DIMN*DIMN];
__device__ bf16 g_woh[DIMN*DIMN], g_wol[DIMN*DIMN];

// ---------------- helpers ----------------------------------------------------
__device__ __forceinline__ uint32_t sm_u32(const void* p) {
    uint32_t a;
    asm("{ .reg .u64 t; cvta.to.shared.u64 t, %1; cvt.u32.u64 %0, t; }"
        : "=r"(a) : "l"(p));
    return a;
}
__device__ __forceinline__ void ldsm4(uint32_t* r, uint32_t a) {
    asm volatile("ldmatrix.sync.aligned.m8n8.x4.shared.b16 {%0,%1,%2,%3}, [%4];"
                 : "=r"(r[0]), "=r"(r[1]), "=r"(r[2]), "=r"(r[3]) : "r"(a));
}
__device__ __forceinline__ void ldsm4t(uint32_t* r, uint32_t a) {
    asm volatile("ldmatrix.sync.aligned.m8n8.x4.trans.shared.b16 {%0,%1,%2,%3}, [%4];"
                 : "=r"(r[0]), "=r"(r[1]), "=r"(r[2]), "=r"(r[3]) : "r"(a));
}
__device__ __forceinline__ void mma_bf(float* c, const uint32_t* a, uint32_t b0,
                                       uint32_t b1) {
    asm volatile(
        "mma.sync.aligned.m16n8k16.row.col.f32.bf16.bf16.f32 "
        "{%0,%1,%2,%3}, {%4,%5,%6,%7}, {%8,%9}, {%0,%1,%2,%3};"
        : "+f"(c[0]), "+f"(c[1]), "+f"(c[2]), "+f"(c[3])
        : "r"(a[0]), "r"(a[1]), "r"(a[2]), "r"(a[3]), "r"(b0), "r"(b1));
}
__device__ __forceinline__ float ex2f(float x) {
    float y;
    asm("ex2.approx.ftz.f32 %0, %1;" : "=f"(y) : "f"(x));
    return y;
}
// pack: result.lo = a, result.hi = b
__device__ __forceinline__ uint32_t packbf(float a, float b) {
    uint32_t r;
    asm("cvt.rn.satfinite.bf16x2.f32 %0, %1, %2;" : "=r"(r) : "f"(b), "f"(a));
    return r;
}
__device__ __forceinline__ float lo_f(uint32_t h) { return __uint_as_float(h << 16); }
__device__ __forceinline__ float hi_f(uint32_t h) {
    return __uint_as_float(h & 0xffff0000u);
}
__device__ __forceinline__ void cpa16cg(uint32_t dst, const void* src) {
    asm volatile("cp.async.cg.shared.global [%0], [%1], 16;"
                 :: "r"(dst), "l"(__cvta_generic_to_global(src)));
}
#define CP_COMMIT asm volatile("cp.async.commit_group;" ::: "memory")
#define CP_WAIT0  asm volatile("cp.async.wait_group 0;" ::: "memory")
#define CP_WAIT1  asm volatile("cp.async.wait_group 1;" ::: "memory")

// swizzled offset for 16B chunk c in 128B row r
#define SWZ(r, c) ((uint32_t)((r) * 128) + ((uint32_t)((c) ^ ((r) & 7)) << 4))

// ---------------------------------------------------------------------------
// split fp32 -> bf16 hi + lo (x ~= hi + lo). merged variants.
// ---------------------------------------------------------------------------
__device__ __forceinline__ void split_body(const float* __restrict__ s,
                                           bf16* __restrict__ h,
                                           bf16* __restrict__ l) {
    int i = (blockIdx.x * 256 + threadIdx.x) * 4;
    float4 v = *(const float4*)&s[i];
    uint32_t h01 = packbf(v.x, v.y);
    uint32_t h23 = packbf(v.z, v.w);
    uint32_t l01 = packbf(v.x - lo_f(h01), v.y - hi_f(h01));
    uint32_t l23 = packbf(v.z - lo_f(h23), v.w - hi_f(h23));
    *(uint2*)&h[i] = make_uint2(h01, h23);
    *(uint2*)&l[i] = make_uint2(l01, l23);
}
__global__ __launch_bounds__(256) void split_x2(
    const float* __restrict__ s0, bf16* __restrict__ h0, bf16* __restrict__ l0,
    const float* __restrict__ s1, bf16* __restrict__ h1, bf16* __restrict__ l1) {
    if (blockIdx.y == 0) split_body(s0, h0, l0);
    else                 split_body(s1, h1, l1);
}
__global__ __launch_bounds__(256) void split_w4(
    const float* __restrict__ s0, bf16* __restrict__ h0, bf16* __restrict__ l0,
    const float* __restrict__ s1, bf16* __restrict__ h1, bf16* __restrict__ l1,
    const float* __restrict__ s2, bf16* __restrict__ h2, bf16* __restrict__ l2,
    const float* __restrict__ s3, bf16* __restrict__ h3, bf16* __restrict__ l3) {
    switch (blockIdx.y) {
        case 0: split_body(s0, h0, l0); break;
        case 1: split_body(s1, h1, l1); break;
        case 2: split_body(s2, h2, l2); break;
        default: split_body(s3, h3, l3); break;
    }
}

// ---------------------------------------------------------------------------
// bf16-split x3 GEMM, 64x64 tile, 2-stage pipeline, 128B swizzled rows.
// (R12 measured config: 37.5us, tensor=56%.)
// Stage (32 KB): Ah +0, Al +8192, Wh +16384, Wl +24576.
// ---------------------------------------------------------------------------
#define GST 32768
#define GEMM_SMEM (2 * GST)   /* 65536 -> 3 CTAs/SM */

__global__ __launch_bounds__(128, 3) void gemm_tc(
    const bf16* __restrict__ Ah, const bf16* __restrict__ Al,
    const bf16* __restrict__ Wh, const bf16* __restrict__ Wl,
    bf16* __restrict__ Ch, bf16* __restrict__ Cl,
    float* __restrict__ Cf, const float* __restrict__ bias, float scale) {
    extern __shared__ char smem[];
    const uint32_t sb = sm_u32(smem);
    const int tid = threadIdx.x, w = tid >> 5, l = tid & 31;
    const int m0 = blockIdx.x * 64, n0 = blockIdx.y * 64;

    auto issue = [&](int kc, uint32_t stb) {
#pragma unroll
        for (int p = 0; p < 16; p++) {
            int li = tid + 128 * p;
            int arr = li >> 9;
            int rem = li & 511;
            int r = rem >> 3, c = rem & 7;
            const bf16* base = (arr == 0) ? Ah : (arr == 1) ? Al : (arr == 2) ? Wh : Wl;
            int row0 = (arr < 2) ? m0 : n0;
            cpa16cg(sb + stb + (uint32_t)arr * 8192 + SWZ(r, c),
                    base + (size_t)(row0 + r) * DIMN + kc * 64 + c * 8);
        }
        CP_COMMIT;
    };

    float acc[8][4];
#pragma unroll
    for (int i = 0; i < 8; i++)
#pragma unroll
        for (int j = 0; j < 4; j++) acc[i][j] = 0.f;

    issue(0, 0);
    for (int kc = 0; kc < 8; kc++) {
        if (kc + 1 < 8) {
            issue(kc + 1, (uint32_t)((kc + 1) & 1) * GST);
            CP_WAIT1;
        } else {
            CP_WAIT0;
        }
        __syncthreads();
        const uint32_t stb = sb + (uint32_t)(kc & 1) * GST;

        uint32_t ah[16], al[16];
#pragma unroll
        for (int kt = 0; kt < 4; kt++) {
            int row = w * 16 + (l & 15);
            int cc = kt * 2 + (l >> 4);
            uint32_t aa = stb + SWZ(row, cc);
            ldsm4(&ah[kt * 4], aa);
            ldsm4(&al[kt * 4], aa + 8192);
        }
#pragma unroll
        for (int ntp = 0; ntp < 4; ntp++) {
#pragma unroll
            for (int kt = 0; kt < 4; kt++) {
                uint32_t bh[4], bl[4];
                int row = ntp * 16 + ((l >> 4) << 3) + (l & 7);
                int cc = kt * 2 + ((l >> 3) & 1);
                uint32_t ba = stb + 16384 + SWZ(row, cc);
                ldsm4(bh, ba);
                ldsm4(bl, ba + 8192);
                mma_bf(acc[2 * ntp], &ah[kt * 4], bh[0], bh[1]);
                mma_bf(acc[2 * ntp], &ah[kt * 4], bl[0], bl[1]);
                mma_bf(acc[2 * ntp], &al[kt * 4], bh[0], bh[1]);
                mma_bf(acc[2 * ntp + 1], &ah[kt * 4], bh[2], bh[3]);
                mma_bf(acc[2 * ntp + 1], &ah[kt * 4], bl[2], bl[3]);
                mma_bf(acc[2 * ntp + 1], &al[kt * 4], bh[2], bh[3]);
            }
        }
        __syncthreads();
    }

    const int r0 = m0 + w * 16 + (l >> 2);
    const int c0 = n0 + 2 * (l & 3);
#pragma unroll
    for (int nt = 0; nt < 8; nt++) {
        int cc = c0 + nt * 8;
        float v0 = acc[nt][0] * scale, v1 = acc[nt][1] * scale;
        float v2 = acc[nt][2] * scale, v3 = acc[nt][3] * scale;
        if (bias) {
            float b0 = bias[cc], b1 = bias[cc + 1];
            v0 += b0; v1 += b1; v2 += b0; v3 += b1;
        }
        if (Cf) {
            *(float2*)&Cf[(size_t)r0 * DIMN + cc] = make_float2(v0, v1);
            *(float2*)&Cf[(size_t)(r0 + 8) * DIMN + cc] = make_float2(v2, v3);
        } else {
            uint32_t h01 = packbf(v0, v1);
            uint32_t h23 = packbf(v2, v3);
            uint32_t l01 = packbf(v0 - lo_f(h01), v1 - hi_f(h01));
            uint32_t l23 = packbf(v2 - lo_f(h23), v3 - hi_f(h23));
            *(uint32_t*)&Ch[(size_t)r0 * DIMN + cc] = h01;
            *(uint32_t*)&Ch[(size_t)(r0 + 8) * DIMN + cc] = h23;
            *(uint32_t*)&Cl[(size_t)r0 * DIMN + cc] = l01;
            *(uint32_t*)&Cl[(size_t)(r0 + 8) * DIMN + cc] = l23;
        }
    }
}

// ---------------------------------------------------------------------------
// Fused K+V projection GEMM: one A(ctx) tile feeds both W_K and W_V.
// Same 64x64 structure as gemm_tc; 192 MMAs/warp/chunk (2x chain length).
// Stage (48 KB): Ah +0, Al +8192, WKh +16384, WKl +24576, WVh +32768,
// WVl +40960. 2 stages = 96 KB -> 2 CTAs/SM (launch_bounds(128,2): regs free).
// ---------------------------------------------------------------------------
#define KVST 49152
#define KV_SMEM (2 * KVST)   /* 98304 */

__global__ __launch_bounds__(128, 2) void gemm_kv(
    const bf16* __restrict__ Ah, const bf16* __restrict__ Al,
    const bf16* __restrict__ WKh, const bf16* __restrict__ WKl,
    const bf16* __restrict__ WVh, const bf16* __restrict__ WVl,
    bf16* __restrict__ Kh, bf16* __restrict__ Kl,
    bf16* __restrict__ Vh, bf16* __restrict__ Vl) {
    extern __shared__ char smem[];
    const uint32_t sb = sm_u32(smem);
    const int tid = threadIdx.x, w = tid >> 5, l = tid & 31;
    const int m0 = blockIdx.x * 64, n0 = blockIdx.y * 64;

    auto issue = [&](int kc, uint32_t stb) {
#pragma unroll
        for (int p = 0; p < 24; p++) {
            int li = tid + 128 * p;
            int arr = li >> 9;   // 0..5
            int rem = li & 511;
            int r = rem >> 3, c = rem & 7;
            const bf16* base = (arr == 0) ? Ah : (arr == 1) ? Al
                             : (arr == 2) ? WKh : (arr == 3) ? WKl
                             : (arr == 4) ? WVh : WVl;
            int row0 = (arr < 2) ? m0 : n0;
            cpa16cg(sb + stb + (uint32_t)arr * 8192 + SWZ(r, c),
                    base + (size_t)(row0 + r) * DIMN + kc * 64 + c * 8);
        }
        CP_COMMIT;
    };

    float accK[8][4], accV[8][4];
#pragma unroll
    for (int i = 0; i < 8; i++)
#pragma unroll
        for (int j = 0; j < 4; j++) { accK[i][j] = 0.f; accV[i][j] = 0.f; }

    issue(0, 0);
    for (int kc = 0; kc < 8; kc++) {
        if (kc + 1 < 8) {
            issue(kc + 1, (uint32_t)((kc + 1) & 1) * KVST);
            CP_WAIT1;
        } else {
            CP_WAIT0;
        }
        __syncthreads();
        const uint32_t stb = sb + (uint32_t)(kc & 1) * KVST;

        uint32_t ah[16], al[16];
#pragma unroll
        for (int kt = 0; kt < 4; kt++) {
            int row = w * 16 + (l & 15);
            int cc = kt * 2 + (l >> 4);
            uint32_t aa = stb + SWZ(row, cc);
            ldsm4(&ah[kt * 4], aa);
            ldsm4(&al[kt * 4], aa + 8192);
        }
#pragma unroll
        for (int ntp = 0; ntp < 4; ntp++) {
#pragma unroll
            for (int kt = 0; kt < 4; kt++) {
                int row = ntp * 16 + ((l >> 4) << 3) + (l & 7);
                int cc = kt * 2 + ((l >> 3) & 1);
                uint32_t bh[4], bl[4];
                // K weights
                uint32_t ba = stb + 16384u + SWZ(row, cc);
                ldsm4(bh, ba);
                ldsm4(bl, ba + 8192);
                mma_bf(accK[2 * ntp], &ah[kt * 4], bh[0], bh[1]);
                mma_bf(accK[2 * ntp], &ah[kt * 4], bl[0], bl[1]);
                mma_bf(accK[2 * ntp], &al[kt * 4], bh[0], bh[1]);
                mma_bf(accK[2 * ntp + 1], &ah[kt * 4], bh[2], bh[3]);
                mma_bf(accK[2 * ntp + 1], &ah[kt * 4], bl[2], bl[3]);
                mma_bf(accK[2 * ntp + 1], &al[kt * 4], bh[2], bh[3]);
                // V weights
                uint32_t bv = stb + 32768u + SWZ(row, cc);
                ldsm4(bh, bv);
                ldsm4(bl, bv + 8192);
                mma_bf(accV[2 * ntp], &ah[kt * 4], bh[0], bh[1]);
                mma_bf(accV[2 * ntp], &ah[kt * 4], bl[0], bl[1]);
                mma_bf(accV[2 * ntp], &al[kt * 4], bh[0], bh[1]);
                mma_bf(accV[2 * ntp + 1], &ah[kt * 4], bh[2], bh[3]);
                mma_bf(accV[2 * ntp + 1], &ah[kt * 4], bl[2], bl[3]);
                mma_bf(accV[2 * ntp + 1], &al[kt * 4], bh[2], bh[3]);
            }
        }
        __syncthreads();
    }

    const int r0 = m0 + w * 16 + (l >> 2);
    const int c0 = n0 + 2 * (l & 3);
#pragma unroll
    for (int nt = 0; nt < 8; nt++) {
        int cc = c0 + nt * 8;
        {
            float v0 = accK[nt][0], v1 = accK[nt][1];
            float v2 = accK[nt][2], v3 = accK[nt][3];
            uint32_t h01 = packbf(v0, v1), h23 = packbf(v2, v3);
            uint32_t l01 = packbf(v0 - lo_f(h01), v1 - hi_f(h01));
            uint32_t l23 = packbf(v2 - lo_f(h23), v3 - hi_f(h23));
            *(uint32_t*)&Kh[(size_t)r0 * DIMN + cc] = h01;
            *(uint32_t*)&Kh[(size_t)(r0 + 8) * DIMN + cc] = h23;
            *(uint32_t*)&Kl[(size_t)r0 * DIMN + cc] = l01;
            *(uint32_t*)&Kl[(size_t)(r0 + 8) * DIMN + cc] = l23;
        }
        {
            float v0 = accV[nt][0], v1 = accV[nt][1];
            float v2 = accV[nt][2], v3 = accV[nt][3];
            uint32_t h01 = packbf(v0, v1), h23 = packbf(v2, v3);
            uint32_t l01 = packbf(v0 - lo_f(h01), v1 - hi_f(h01));
            uint32_t l23 = packbf(v2 - lo_f(h23), v3 - hi_f(h23));
            *(uint32_t*)&Vh[(size_t)r0 * DIMN + cc] = h01;
            *(uint32_t*)&Vh[(size_t)(r0 + 8) * DIMN + cc] = h23;
            *(uint32_t*)&Vl[(size_t)r0 * DIMN + cc] = l01;
            *(uint32_t*)&Vl[(size_t)(r0 + 8) * DIMN + cc] = l23;
        }
    }
}

// ---------------------------------------------------------------------------
// Flash attention (R12 measured config): bf16-split x3, log2-domain softmax,
// 2-stage cp.async pipeline, XOR-swizzled 128B rows, Q overlaid in stage 1.
// 64 KB smem -> 3 CTAs/SM. grid (SEQ/64, NH, NB), 128 threads.
// Stage (32 KB): KH +0, KL +8192, VH +16384, VL +24576.
// ---------------------------------------------------------------------------
#define NCHUNK (SEQ / 64)
#define STG 32768
#define ATT_SMEM (2 * STG)   /* 65536 */

__global__ __launch_bounds__(128, 3) void attn_tc(
    const bf16* __restrict__ Qh, const bf16* __restrict__ Ql,
    const bf16* __restrict__ Kh, const bf16* __restrict__ Kl,
    const bf16* __restrict__ Vh, const bf16* __restrict__ Vl,
    bf16* __restrict__ Ahi, bf16* __restrict__ Alo) {
    extern __shared__ char smem[];
    const uint32_t sb = sm_u32(smem);
    const int tid = threadIdx.x, w = tid >> 5, l = tid & 31;
    const int q0 = blockIdx.x * 64;
    const int h = blockIdx.y, b = blockIdx.z;
    const size_t headoff = (size_t)h * DH;
    const size_t qrow0 = (size_t)(b * SEQ + q0);
    const size_t krow0 = (size_t)(b * SEQ);

    auto kvissue = [&](int chunk, uint32_t stb) {
#pragma unroll
        for (int p = 0; p < 16; p++) {
            int li = tid + 128 * p;
            int arr = li >> 9;
            int rem = li & 511;
            int r = rem >> 3, c = rem & 7;
            const bf16* base = (arr == 0) ? Kh : (arr == 1) ? Kl : (arr == 2) ? Vh : Vl;
            cpa16cg(sb + stb + (uint32_t)arr * 8192 + SWZ(r, c),
                    base + (krow0 + chunk * 64 + r) * DIMN + headoff + c * 8);
        }
        CP_COMMIT;
    };

    // Q (hi/lo) into stage 1; chunk 0 into stage 0
#pragma unroll
    for (int p = 0; p < 8; p++) {
        int li = tid + 128 * p;
        int arr = li >> 9;
        int rem = li & 511;
        int r = rem >> 3, c = rem & 7;
        const bf16* src = (arr ? Ql : Qh) + (qrow0 + r) * DIMN + headoff + c * 8;
        cpa16cg(sb + STG + (uint32_t)arr * 8192 + SWZ(r, c), src);
    }
    CP_COMMIT;
    kvissue(0, 0);
    CP_WAIT0;
    __syncthreads();

    // extract Q fragments from stage 1 (held in registers for all chunks)
    uint32_t aqh[16], aql[16];
#pragma unroll
    for (int kt = 0; kt < 4; kt++) {
        int row = w * 16 + (l & 15);
        int cc = kt * 2 + (l >> 4);
        uint32_t aa = sb + STG + SWZ(row, cc);
        ldsm4(&aqh[kt * 4], aa);
        ldsm4(&aql[kt * 4], aa + 8192);
    }
    __syncthreads();  // stage 1 free -> prefetch chunk 1 into it
    kvissue(1, STG);

    float o[8][4];
#pragma unroll
    for (int i = 0; i < 8; i++)
#pragma unroll
        for (int j = 0; j < 4; j++) o[i][j] = 0.f;
    float ls0 = 0.f, ls1 = 0.f;

    for (int ch = 0; ch < NCHUNK; ch++) {
        if (ch + 1 < NCHUNK) CP_WAIT1; else CP_WAIT0;
        __syncthreads();
        const uint32_t stb = sb + (uint32_t)(ch & 1) * STG;

        // ---- S = Q @ K^T (x3 terms), ldsm4-paired B fragments ----
        float s[8][4];
#pragma unroll
        for (int i = 0; i < 8; i++)
#pragma unroll
            for (int j = 0; j < 4; j++) s[i][j] = 0.f;
#pragma unroll
        for (int ntp = 0; ntp < 4; ntp++) {
#pragma unroll
            for (int kt = 0; kt < 4; kt++) {
                uint32_t bh[4], bl[4];
                int row = ntp * 16 + ((l >> 4) << 3) + (l & 7);
                int cc = kt * 2 + ((l >> 3) & 1);
                uint32_t ba = stb + SWZ(row, cc);
                ldsm4(bh, ba);
                ldsm4(bl, ba + 8192);
                mma_bf(s[2 * ntp], &aqh[kt * 4], bh[0], bh[1]);
                mma_bf(s[2 * ntp], &aqh[kt * 4], bl[0], bl[1]);
                mma_bf(s[2 * ntp], &aql[kt * 4], bh[0], bh[1]);
                mma_bf(s[2 * ntp + 1], &aqh[kt * 4], bh[2], bh[3]);
                mma_bf(s[2 * ntp + 1], &aqh[kt * 4], bl[2], bl[3]);
                mma_bf(s[2 * ntp + 1], &aql[kt * 4], bh[2], bh[3]);
            }
        }

        // ---- p = 2^s ; split to bf16 hi/lo, build A-fragments for P@V ----
        uint32_t pah[16], pal[16];
#pragma unroll
        for (int nt = 0; nt < 8; nt++) {
            float p0 = ex2f(s[nt][0]);
            float p1 = ex2f(s[nt][1]);
            float p2 = ex2f(s[nt][2]);
            float p3 = ex2f(s[nt][3]);
            ls0 += p0 + p1;
            ls1 += p2 + p3;
            uint32_t h01 = packbf(p0, p1);
            uint32_t h23 = packbf(p2, p3);
            uint32_t l01 = packbf(p0 - lo_f(h01), p1 - hi_f(h01));
            uint32_t l23 = packbf(p2 - lo_f(h23), p3 - hi_f(h23));
            int kt = nt >> 1, j = (nt & 1) * 2;
            pah[kt * 4 + j] = h01;
            pah[kt * 4 + j + 1] = h23;
            pal[kt * 4 + j] = l01;
            pal[kt * 4 + j + 1] = l23;
        }

        // ---- O += P @ V (x3 terms) ----
#pragma unroll
        for (int kt = 0; kt < 4; kt++) {
#pragma unroll
            for (int ntp = 0; ntp < 4; ntp++) {
                uint32_t vh[4], vl[4];
                int row = kt * 16 + (l & 7) + ((l >> 3) & 1) * 8;
                int cc = ntp * 2 + (l >> 4);
                uint32_t va = stb + 16384 + SWZ(row, cc);
                ldsm4t(vh, va);
                ldsm4t(vl, va + 8192);
                mma_bf(o[2 * ntp], &pah[kt * 4], vh[0], vh[1]);
                mma_bf(o[2 * ntp], &pah[kt * 4], vl[0], vl[1]);
                mma_bf(o[2 * ntp], &pal[kt * 4], vh[0], vh[1]);
                mma_bf(o[2 * ntp + 1], &pah[kt * 4], vh[2], vh[3]);
                mma_bf(o[2 * ntp + 1], &pah[kt * 4], vl[2], vl[3]);
                mma_bf(o[2 * ntp + 1], &pal[kt * 4], vh[2], vh[3]);
            }
        }
        __syncthreads();  // all warps done with stage (ch&1)
        if (ch + 2 < NCHUNK) kvissue(ch + 2, stb - sb);
    }

    // row-sum reduce across the quad (threads sharing a row)
#pragma unroll
    for (int off = 1; off <= 2; off <<= 1) {
        ls0 += __shfl_xor_sync(0xffffffffu, ls0, off);
        ls1 += __shfl_xor_sync(0xffffffffu, ls1, off);
    }
    const float i0 = 1.0f / ls0, i1 = 1.0f / ls1;
    const size_t r0 = qrow0 + w * 16 + (l >> 2);
    const int c0 = (int)headoff + 2 * (l & 3);
#pragma unroll
    for (int nt = 0; nt < 8; nt++) {
        int cc = c0 + nt * 8;
        float p0 = o[nt][0] * i0, p1 = o[nt][1] * i0;
        float p2 = o[nt][2] * i1, p3 = o[nt][3] * i1;
        uint32_t h01 = packbf(p0, p1);
        uint32_t h23 = packbf(p2, p3);
        uint32_t l01 = packbf(p0 - lo_f(h01), p1 - hi_f(h01));
        uint32_t l23 = packbf(p2 - lo_f(h23), p3 - hi_f(h23));
        *(uint32_t*)&Ahi[r0 * DIMN + cc] = h01;
        *(uint32_t*)&Ahi[(r0 + 8) * DIMN + cc] = h23;
        *(uint32_t*)&Alo[r0 * DIMN + cc] = l01;
        *(uint32_t*)&Alo[(r0 + 8) * DIMN + cc] = l23;
    }
}

// ---------------------------------------------------------------------------
extern "C" void kernel_launch(void* const* d_in, const int* in_sizes, int n_in,
                              void* d_out, int out_size) {
    const float* x     = (const float*)d_in[0];
    const float* ctx   = (const float*)d_in[1];
    const float* w_q   = (const float*)d_in[2];
    const float* w_k   = (const float*)d_in[3];
    const float* w_v   = (const float*)d_in[4];
    const float* w_out = (const float*)d_in[5];
    const float* b_out = (const float*)d_in[6];
    float* out = (float*)d_out;

    bf16 *xh, *xl, *ch, *cl, *qh, *ql, *kh, *kl, *vh, *vl, *ah, *al;
    bf16 *wqh, *wql, *wkh, *wkl, *wvh, *wvl, *woh, *wol;
    cudaGetSymbolAddress((void**)&xh, g_xh);   cudaGetSymbolAddress((void**)&xl, g_xl);
    cudaGetSymbolAddress((void**)&ch, g_ch);   cudaGetSymbolAddress((void**)&cl, g_cl);
    cudaGetSymbolAddress((void**)&qh, g_qh);   cudaGetSymbolAddress((void**)&ql, g_ql);
    cudaGetSymbolAddress((void**)&kh, g_kh);   cudaGetSymbolAddress((void**)&kl, g_kl);
    cudaGetSymbolAddress((void**)&vh, g_vh);   cudaGetSymbolAddress((void**)&vl, g_vl);
    cudaGetSymbolAddress((void**)&ah, g_ah);   cudaGetSymbolAddress((void**)&al, g_al);
    cudaGetSymbolAddress((void**)&wqh, g_wqh); cudaGetSymbolAddress((void**)&wql, g_wql);
    cudaGetSymbolAddress((void**)&wkh, g_wkh); cudaGetSymbolAddress((void**)&wkl, g_wkl);
    cudaGetSymbolAddress((void**)&wvh, g_wvh); cudaGetSymbolAddress((void**)&wvl, g_wvl);
    cudaGetSymbolAddress((void**)&woh, g_woh); cudaGetSymbolAddress((void**)&wol, g_wol);

    cudaFuncSetAttribute(attn_tc, cudaFuncAttributeMaxDynamicSharedMemorySize,
                         ATT_SMEM);
    cudaFuncSetAttribute(gemm_tc, cudaFuncAttributeMaxDynamicSharedMemorySize,
                         GEMM_SMEM);
    cudaFuncSetAttribute(gemm_kv, cudaFuncAttributeMaxDynamicSharedMemorySize,
                         KV_SMEM);

    const int nbig = ROWSZ * DIMN / 1024;   // 4096 blocks
    const int nsml = DIMN * DIMN / 1024;    // 256 blocks
    split_x2<<<dim3(nbig, 2), 256>>>(x, xh, xl, ctx, ch, cl);
    split_w4<<<dim3(nsml, 4), 256>>>(w_q, wqh, wql, w_k, wkh, wkl,
                                     w_v, wvh, wvl, w_out, woh, wol);

    dim3 gg(ROWSZ / 64, DIMN / 64);
    gemm_tc<<<gg, 128, GEMM_SMEM>>>(xh, xl, wqh, wql, qh, ql, nullptr, nullptr, QSCALE);
    gemm_kv<<<gg, 128, KV_SMEM>>>(ch, cl, wkh, wkl, wvh, wvl, kh, kl, vh, vl);

    attn_tc<<<dim3(SEQ / 64, NH, NB), 128, ATT_SMEM>>>(qh, ql, kh, kl, vh, vl,
                                                       ah, al);

    gemm_tc<<<gg, 128, GEMM_SMEM>>>(ah, al, woh, wol, nullptr, nullptr, out, b_out, 1.0f);
}